// round 15
// baseline (speedup 1.0000x reference)
#include <cuda_runtime.h>
#include <cuda_bf16.h>
#include <cuda_fp8.h>
#include <cstdint>
#include <math.h>

#define BATCH 32
#define CDIM  384
#define HDIM  56
#define HWSZ  3136
#define NTOK  100352
#define HID   1536
#define HEADS 8
#define HD    48
#define GSZ   7
#define SPR   8

typedef __nv_bfloat16 bf16;
typedef __nv_fp8_e4m3 fp8;

#define WSCALE     64.0f
#define INV_WSCALE 0.015625f

// ---------------- scratch ----------------
__device__ float g_xt  [(size_t)NTOK * CDIM];
__device__ fp8   g_h8  [(size_t)NTOK * CDIM];
__device__ bf16  g_qkvb[(size_t)NTOK * 3 * CDIM];
__device__ bf16  g_mb  [(size_t)NTOK * HID];
__device__ fp8   g_mg8 [(size_t)NTOK * HID];
__device__ fp8   g_wqkv8 [3 * CDIM * CDIM];
__device__ fp8   g_wproj8[CDIM * CDIM];
__device__ fp8   g_wfc18 [HID * CDIM];
__device__ fp8   g_wfc28 [CDIM * HID];

__device__ __forceinline__ unsigned int saddr(const void* p) {
    return (unsigned int)__cvta_generic_to_shared(p);
}
__device__ __forceinline__ void cp16(unsigned int dst, const void* src) {
    asm volatile("cp.async.cg.shared.global [%0], [%1], 16;" :: "r"(dst), "l"(src));
}

// ================== FP8 e4m3 tensor-core GEMM ==================
// Block 128x128, 8 warps (warp tile 64x32), BK=128 bytes, 3-stage ring, 2 CTAs/SM.
// Pointer-increment loader + hoisted ldmatrix bases.
#define PADB 144
#define STG 3
#define TILEB (128 * PADB)

template<int EPI>
__global__ __launch_bounds__(256, 2) void gemm_fp8_kernel(
    const fp8* __restrict__ A, const fp8* __restrict__ Bw,
    const float* __restrict__ bias, const float* __restrict__ res,
    const float* __restrict__ gamma, void* __restrict__ Cout,
    int M, int N, int K)
{
    extern __shared__ char sm8[];
    char* As = sm8;
    char* Bs = sm8 + STG * TILEB;

    const int tid  = threadIdx.x;
    const int lane = tid & 31;
    const int warp = tid >> 5;
    const int wm   = (warp >> 2) * 64;
    const int wn   = (warp & 3) * 32;
    const int bm   = blockIdx.y * 128;
    const int bn   = blockIdx.x * 128;

    float acc[4][4][4];
#pragma unroll
    for (int i = 0; i < 4; i++)
#pragma unroll
        for (int j = 0; j < 4; j++)
#pragma unroll
            for (int r = 0; r < 4; r++) acc[i][j][r] = 0.f;

    // ---- precomputed loader state ----
    const char* aptr[4];
    const char* bptr[4];
    unsigned int dA0[4], dB0[4];
#pragma unroll
    for (int u = 0; u < 4; u++) {
        int id = u * 256 + tid;
        int row = id >> 3, c = id & 7;
        aptr[u] = (const char*)A + (size_t)(bm + row) * K + c * 16;
        bptr[u] = (const char*)Bw + (size_t)(bn + row) * K + c * 16;
        dA0[u] = saddr(As + row * PADB + c * 16);
        dB0[u] = saddr(Bs + row * PADB + c * 16);
    }

    // ---- hoisted ldmatrix bases (stage-0) ----
    const int a_row  = lane & 15;
    const int a_kb   = (lane >> 4) * 16;
    const int b_nrow = ((lane >> 4) * 8) + (lane & 7);
    const int b_kb   = ((lane >> 3) & 1) * 16;
    unsigned int sm_a[4], sm_b[2];
#pragma unroll
    for (int i = 0; i < 4; i++)
        sm_a[i] = saddr(As + (wm + i * 16 + a_row) * PADB + a_kb);
#pragma unroll
    for (int j2 = 0; j2 < 2; j2++)
        sm_b[j2] = saddr(Bs + (wn + j2 * 16 + b_nrow) * PADB + b_kb);

    const int iters = K / 128;

    auto load_stage = [&](int s) {
        const unsigned int so = (unsigned int)(s * TILEB);
#pragma unroll
        for (int u = 0; u < 4; u++) {
            cp16(dA0[u] + so, aptr[u]);
            aptr[u] += 128;
        }
#pragma unroll
        for (int u = 0; u < 4; u++) {
            cp16(dB0[u] + so, bptr[u]);
            bptr[u] += 128;
        }
        asm volatile("cp.async.commit_group;");
    };

    // prologue: stages 0..STG-2
    load_stage(0);
    if (iters > 1) load_stage(1);

    int sload = 2;   // next stage slot to fill
    for (int it = 0; it < iters; it++) {
        if (it + STG - 1 < iters) {
            load_stage(sload);
            sload = (sload == STG - 1) ? 0 : sload + 1;
        }
        // wait for stage it: allowed pending = min(STG-1, iters-1-it)
        if (it + STG - 1 < iters)
            asm volatile("cp.async.wait_group 2;" ::: "memory");
        else if (it + STG - 2 < iters)
            asm volatile("cp.async.wait_group 1;" ::: "memory");
        else
            asm volatile("cp.async.wait_group 0;" ::: "memory");
        __syncthreads();

        const int scur = it % STG;
        const unsigned int so = (unsigned int)(scur * TILEB);

#pragma unroll
        for (int ks = 0; ks < 4; ks++) {
            unsigned int a[4][4];
#pragma unroll
            for (int i = 0; i < 4; i++) {
                unsigned int ad = sm_a[i] + so + ks * 32;
                asm volatile("ldmatrix.sync.aligned.m8n8.x4.shared.b16 {%0,%1,%2,%3}, [%4];"
                             : "=r"(a[i][0]), "=r"(a[i][1]), "=r"(a[i][2]), "=r"(a[i][3])
                             : "r"(ad));
            }
            unsigned int b[4][2];
#pragma unroll
            for (int j2 = 0; j2 < 2; j2++) {
                unsigned int bd = sm_b[j2] + so + ks * 32;
                unsigned int r0, r1, r2, r3;
                asm volatile("ldmatrix.sync.aligned.m8n8.x4.shared.b16 {%0,%1,%2,%3}, [%4];"
                             : "=r"(r0), "=r"(r1), "=r"(r2), "=r"(r3) : "r"(bd));
                b[j2 * 2 + 0][0] = r0; b[j2 * 2 + 0][1] = r1;
                b[j2 * 2 + 1][0] = r2; b[j2 * 2 + 1][1] = r3;
            }
#pragma unroll
            for (int i = 0; i < 4; i++)
#pragma unroll
                for (int j = 0; j < 4; j++)
                    asm volatile(
                        "mma.sync.aligned.m16n8k32.row.col.f32.e4m3.e4m3.f32 "
                        "{%0,%1,%2,%3}, {%4,%5,%6,%7}, {%8,%9}, {%0,%1,%2,%3};"
                        : "+f"(acc[i][j][0]), "+f"(acc[i][j][1]),
                          "+f"(acc[i][j][2]), "+f"(acc[i][j][3])
                        : "r"(a[i][0]), "r"(a[i][1]), "r"(a[i][2]), "r"(a[i][3]),
                          "r"(b[j][0]), "r"(b[j][1]));
        }
        __syncthreads();
    }

    // -------- epilogue --------
    const int rbase = bm + wm + (lane >> 2);
    const int cbase = bn + wn + (lane & 3) * 2;
#pragma unroll
    for (int j = 0; j < 4; j++) {
        const int c = cbase + j * 8;
        const float b0 = bias ? bias[c] : 0.f;
        const float b1 = bias ? bias[c + 1] : 0.f;
        float g0 = 1.f, g1 = 1.f;
        if (EPI == 1) { g0 = gamma[c]; g1 = gamma[c + 1]; }
#pragma unroll
        for (int i = 0; i < 4; i++) {
#pragma unroll
            for (int h = 0; h < 2; h++) {
                const int r = rbase + i * 16 + h * 8;
                const float v0 = acc[i][j][h * 2 + 0] * INV_WSCALE + b0;
                const float v1 = acc[i][j][h * 2 + 1] * INV_WSCALE + b1;
                if (EPI == 0) {
                    bf16* C = (bf16*)Cout;
                    __nv_bfloat162 pv;
                    pv.x = __float2bfloat16(v0);
                    pv.y = __float2bfloat16(v1);
                    *(__nv_bfloat162*)&C[(size_t)r * N + c] = pv;
                } else {
                    float* C = (float*)Cout;
                    float2 rr = *(const float2*)&res[(size_t)r * N + c];
                    float2 o;
                    o.x = rr.x + g0 * v0;
                    o.y = rr.y + g1 * v1;
                    *(float2*)&C[(size_t)r * N + c] = o;
                }
            }
        }
    }
}
#define GEMM_SMEM (STG * 2 * TILEB)

// ---------------- merged weight transpose+convert ----------------
__global__ void wconv_all_kernel(const float* __restrict__ qkv_w, const float* __restrict__ proj_w,
                                 const float* __restrict__ fc1_w, const float* __restrict__ fc2_w,
                                 fp8* __restrict__ wq, fp8* __restrict__ wp,
                                 fp8* __restrict__ w1, fp8* __restrict__ w2) {
    const float* w; fp8* o; int K, N;
    switch (blockIdx.z) {
        case 0: w = qkv_w;  o = wq; K = CDIM; N = 3 * CDIM; break;
        case 1: w = proj_w; o = wp; K = CDIM; N = CDIM;     break;
        case 2: w = fc1_w;  o = w1; K = CDIM; N = HID;      break;
        default:w = fc2_w;  o = w2; K = HID;  N = CDIM;     break;
    }
    const int n0 = blockIdx.x * 32, k0 = blockIdx.y * 32;
    if (n0 >= N || k0 >= K) return;
    __shared__ float tile[32][33];
#pragma unroll
    for (int i = 0; i < 4; i++)
        tile[threadIdx.y + i * 8][threadIdx.x] =
            w[(size_t)(k0 + threadIdx.y + i * 8) * N + n0 + threadIdx.x];
    __syncthreads();
#pragma unroll
    for (int i = 0; i < 4; i++)
        o[(size_t)(n0 + threadIdx.y + i * 8) * K + k0 + threadIdx.x] =
            fp8(tile[threadIdx.x][threadIdx.y + i * 8] * WSCALE);
}

// ---------------- transposes ----------------
__global__ void transpose_in_kernel(const float* __restrict__ x, float* __restrict__ xt) {
    __shared__ float tile[32][33];
    const int b = blockIdx.z, p0 = blockIdx.x * 32, c0 = blockIdx.y * 32;
    const float* xb = x + (size_t)b * CDIM * HWSZ;
#pragma unroll
    for (int i = 0; i < 4; i++)
        tile[threadIdx.y + i * 8][threadIdx.x] =
            xb[(size_t)(c0 + threadIdx.y + i * 8) * HWSZ + p0 + threadIdx.x];
    __syncthreads();
#pragma unroll
    for (int i = 0; i < 4; i++)
        xt[((size_t)b * HWSZ + p0 + threadIdx.y + i * 8) * CDIM + c0 + threadIdx.x] =
            tile[threadIdx.x][threadIdx.y + i * 8];
}
__global__ void transpose_out_kernel(const float* __restrict__ xt, float* __restrict__ out) {
    __shared__ float tile[32][33];
    const int b = blockIdx.z, p0 = blockIdx.x * 32, c0 = blockIdx.y * 32;
#pragma unroll
    for (int i = 0; i < 4; i++)
        tile[threadIdx.y + i * 8][threadIdx.x] =
            xt[((size_t)b * HWSZ + p0 + threadIdx.y + i * 8) * CDIM + c0 + threadIdx.x];
    __syncthreads();
    float* ob = out + (size_t)b * CDIM * HWSZ;
#pragma unroll
    for (int i = 0; i < 4; i++)
        ob[(size_t)(c0 + threadIdx.y + i * 8) * HWSZ + p0 + threadIdx.x] =
            tile[threadIdx.x][threadIdx.y + i * 8];
}

// ---------------- LayerNorm (fp32 in, fp8 out) ----------------
__global__ void ln_kernel(const float* __restrict__ in, fp8* __restrict__ out,
                          const float* __restrict__ g, const float* __restrict__ b) {
    const int row = blockIdx.x * 8 + threadIdx.y;
    const int lane = threadIdx.x;
    const float* xr = in + (size_t)row * CDIM;
    float v[12];
    float s = 0.f;
#pragma unroll
    for (int i = 0; i < 12; i++) { v[i] = xr[lane + i * 32]; s += v[i]; }
#pragma unroll
    for (int o = 16; o > 0; o >>= 1) s += __shfl_xor_sync(0xffffffffu, s, o);
    const float mean = s * (1.f / CDIM);
    float q = 0.f;
#pragma unroll
    for (int i = 0; i < 12; i++) { float d = v[i] - mean; q += d * d; }
#pragma unroll
    for (int o = 16; o > 0; o >>= 1) q += __shfl_xor_sync(0xffffffffu, q, o);
    const float r = rsqrtf(q * (1.f / CDIM) + 1e-5f);
    fp8* orow = out + (size_t)row * CDIM;
#pragma unroll
    for (int i = 0; i < 12; i++) {
        int c = lane + i * 32;
        orow[c] = fp8((v[i] - mean) * r * g[c] + b[c]);
    }
}

// ---------------- attention: 4 heads/block, reg scores, uint4 KV ----------------
__global__ __launch_bounds__(256) void attn_kernel(const bf16* __restrict__ qkv,
                                                   fp8* __restrict__ o) {
    __shared__ uint4 sk[4][64][6];
    __shared__ uint4 sv[4][64][6];
    __shared__ int   srow[64];

    const int tid = threadIdx.x;
    const int wnd = blockIdx.x;
    const int hg  = blockIdx.y * 4;
    const int b   = wnd / (GSZ * GSZ);
    const int gy  = (wnd / GSZ) % GSZ;
    const int gx  = wnd % GSZ;

    if (tid < 64) {
        int sy = tid / SPR, sx = tid % SPR;
        srow[tid] = b * HWSZ + (sy * GSZ + gy) * HDIM + (sx * GSZ + gx);
    }
    __syncthreads();

    for (int id = tid; id < 1536; id += 256) {
        int h = id / 384, rem = id % 384;
        int t = rem / 6, q = rem % 6;
        size_t base = (size_t)srow[t] * (3 * CDIM) + (hg + h) * HD + q * 8;
        sk[h][t][q] = *(const uint4*)&qkv[base + CDIM];
        sv[h][t][q] = *(const uint4*)&qkv[base + 2 * CDIM];
    }
    __syncthreads();

    const int h = tid >> 6;
    const int t = tid & 63;
    const float scale = 0.14433756729740643f;

    const uint4* qp = (const uint4*)(qkv + (size_t)srow[t] * (3 * CDIM) + (hg + h) * HD);
    uint4 qv[6];
#pragma unroll
    for (int u = 0; u < 6; u++) qv[u] = qp[u];
    const __nv_bfloat162* q2 = (const __nv_bfloat162*)qv;

    float sc[64];
#pragma unroll 4
    for (int j = 0; j < 64; j++) {
        const __nv_bfloat162* kr = (const __nv_bfloat162*)sk[h][j];
        __nv_bfloat162 a2 = __floats2bfloat162_rn(0.f, 0.f);
#pragma unroll
        for (int u = 0; u < 24; u++) a2 = __hfma2(q2[u], kr[u], a2);
        sc[j] = (__low2float(a2) + __high2float(a2)) * scale;
    }

    float mx = -1e30f;
#pragma unroll
    for (int j = 0; j < 64; j++) mx = fmaxf(mx, sc[j]);
    float sum = 0.f;
#pragma unroll
    for (int j = 0; j < 64; j++) {
        float p = __expf(sc[j] - mx);
        sc[j] = p; sum += p;
    }
    const float inv = 1.f / sum;

    __nv_bfloat162 oacc[24];
#pragma unroll
    for (int u = 0; u < 24; u++) oacc[u] = __floats2bfloat162_rn(0.f, 0.f);
#pragma unroll 4
    for (int j = 0; j < 64; j++) {
        const __nv_bfloat162* vr = (const __nv_bfloat162*)sv[h][j];
        __nv_bfloat162 p2 = __float2bfloat162_rn(sc[j]);
#pragma unroll
        for (int u = 0; u < 24; u++) oacc[u] = __hfma2(p2, vr[u], oacc[u]);
    }

    unsigned int packed[12];
#pragma unroll
    for (int u = 0; u < 12; u++) {
        float4 f4 = make_float4(__low2float(oacc[2 * u]) * inv,
                                __high2float(oacc[2 * u]) * inv,
                                __low2float(oacc[2 * u + 1]) * inv,
                                __high2float(oacc[2 * u + 1]) * inv);
        __nv_fp8x4_e4m3 p4(f4);
        packed[u] = *(unsigned int*)&p4;
    }
    uint4* op = (uint4*)(o + (size_t)srow[t] * CDIM + (hg + h) * HD);
#pragma unroll
    for (int u = 0; u < 3; u++)
        op[u] = make_uint4(packed[4 * u], packed[4 * u + 1], packed[4 * u + 2], packed[4 * u + 3]);
}

// ---------------- depthwise 3x3 + GELU, smem row-tiled ----------------
__global__ __launch_bounds__(256) void dwconv_gelu_kernel(
    const bf16* __restrict__ m, const float* __restrict__ w,
    const float* __restrict__ bias, fp8* __restrict__ out)
{
    __shared__ __nv_bfloat162 srow[3][56][64];
    __shared__ __nv_bfloat162 sw[9][64];
    __shared__ float2 sb[64];

    const int tid = threadIdx.x;
    const int y   = blockIdx.x;
    const int cc  = blockIdx.y * 128;
    const int b   = blockIdx.z;

    for (int i = tid; i < 576; i += 256) {
        int t = i / 64, cp = i % 64;
        sw[t][cp] = __floats2bfloat162_rn(w[(cc + 2 * cp) * 9 + t],
                                          w[(cc + 2 * cp + 1) * 9 + t]);
    }
    if (tid < 64) sb[tid] = make_float2(bias[cc + 2 * tid], bias[cc + 2 * tid + 1]);

    const uint4 zero4 = make_uint4(0, 0, 0, 0);
#pragma unroll
    for (int r = 0; r < 3; r++) {
        int yy = y + r - 1;
        const bool ok = (yy >= 0) && (yy < HDIM);
        const bf16* src = m + ((size_t)b * HWSZ + yy * HDIM) * HID + cc;
        for (int id = tid; id < 896; id += 256) {
            int x = id >> 4, c8 = id & 15;
            uint4 v = ok ? *(const uint4*)(src + (size_t)x * HID + c8 * 8) : zero4;
            *(uint4*)&srow[r][x][c8 * 4] = v;
        }
    }
    __syncthreads();

    const float kk = 0.70710678118654752f;
    fp8* orow = out + ((size_t)b * HWSZ + y * HDIM) * HID + cc;

    for (int it = tid; it < 56 * 64; it += 256) {
        int cp = it & 63, x = it >> 6;
        __nv_bfloat162 acc = __floats2bfloat162_rn(0.f, 0.f);
#pragma unroll
        for (int r = 0; r < 3; r++) {
#pragma unroll
            for (int kx = -1; kx <= 1; kx++) {
                int xx = x + kx;
                if (xx >= 0 && xx < HDIM)
                    acc = __hfma2(srow[r][xx][cp], sw[r * 3 + kx + 1][cp], acc);
            }
        }
        float2 bb = sb[cp];
        float a0 = __low2float(acc) + bb.x;
        float a1 = __high2float(acc) + bb.y;
        __nv_fp8x2_e4m3 pv(make_float2(0.5f * a0 * (1.f + erff(a0 * kk)),
                                       0.5f * a1 * (1.f + erff(a1 * kk))));
        *(__nv_fp8x2_e4m3*)&orow[(size_t)x * HID + 2 * cp] = pv;
    }
}

// ---------------- launch ----------------
extern "C" void kernel_launch(void* const* d_in, const int* in_sizes, int n_in,
                              void* d_out, int out_size) {
    const float* x      = (const float*)d_in[0];
    const float* ln1_g  = (const float*)d_in[1];
    const float* ln1_b  = (const float*)d_in[2];
    const float* qkv_w  = (const float*)d_in[3];
    const float* proj_w = (const float*)d_in[4];
    const float* proj_b = (const float*)d_in[5];
    const float* ln2_g  = (const float*)d_in[6];
    const float* ln2_b  = (const float*)d_in[7];
    const float* fc1_w  = (const float*)d_in[8];
    const float* fc1_b  = (const float*)d_in[9];
    const float* dw_w   = (const float*)d_in[10];
    const float* dw_b   = (const float*)d_in[11];
    const float* fc2_w  = (const float*)d_in[12];
    const float* fc2_b  = (const float*)d_in[13];
    const float* gamma1 = (const float*)d_in[14];
    const float* gamma2 = (const float*)d_in[15];
    float* out = (float*)d_out;

    float *xt; bf16 *qkvb, *mb; fp8 *h8, *mg8, *wq, *wp, *w1, *w2;
    cudaGetSymbolAddress((void**)&xt,   g_xt);
    cudaGetSymbolAddress((void**)&h8,   g_h8);
    cudaGetSymbolAddress((void**)&qkvb, g_qkvb);
    cudaGetSymbolAddress((void**)&mb,   g_mb);
    cudaGetSymbolAddress((void**)&mg8,  g_mg8);
    cudaGetSymbolAddress((void**)&wq,   g_wqkv8);
    cudaGetSymbolAddress((void**)&wp,   g_wproj8);
    cudaGetSymbolAddress((void**)&w1,   g_wfc18);
    cudaGetSymbolAddress((void**)&w2,   g_wfc28);

    static bool attr_done = false;
    if (!attr_done) {
        cudaFuncSetAttribute(gemm_fp8_kernel<0>,
                             cudaFuncAttributeMaxDynamicSharedMemorySize, GEMM_SMEM);
        cudaFuncSetAttribute(gemm_fp8_kernel<1>,
                             cudaFuncAttributeMaxDynamicSharedMemorySize, GEMM_SMEM);
        attr_done = true;
    }

    dim3 tb32x8(32, 8);

    wconv_all_kernel<<<dim3(48, 48, 4), tb32x8>>>(qkv_w, proj_w, fc1_w, fc2_w,
                                                  wq, wp, w1, w2);
    transpose_in_kernel<<<dim3(HWSZ / 32, CDIM / 32, BATCH), tb32x8>>>(x, xt);
    ln_kernel<<<NTOK / 8, tb32x8>>>(xt, h8, ln1_g, ln1_b);

    gemm_fp8_kernel<0><<<dim3(1152 / 128, NTOK / 128), 256, GEMM_SMEM>>>(
        h8, wq, nullptr, nullptr, nullptr, qkvb, NTOK, 1152, CDIM);
    attn_kernel<<<dim3(BATCH * GSZ * GSZ, HEADS / 4), 256>>>(qkvb, h8);
    gemm_fp8_kernel<1><<<dim3(CDIM / 128, NTOK / 128), 256, GEMM_SMEM>>>(
        h8, wp, proj_b, xt, gamma1, xt, NTOK, CDIM, CDIM);
    ln_kernel<<<NTOK / 8, tb32x8>>>(xt, h8, ln2_g, ln2_b);
    gemm_fp8_kernel<0><<<dim3(HID / 128, NTOK / 128), 256, GEMM_SMEM>>>(
        h8, w1, fc1_b, nullptr, nullptr, mb, NTOK, HID, CDIM);
    dwconv_gelu_kernel<<<dim3(HDIM, HID / 128, BATCH), 256>>>(mb, dw_w, dw_b, mg8);
    gemm_fp8_kernel<1><<<dim3(CDIM / 128, NTOK / 128), 256, GEMM_SMEM>>>(
        mg8, w2, fc2_b, xt, gamma2, xt, NTOK, CDIM, HID);

    transpose_out_kernel<<<dim3(HWSZ / 32, CDIM / 32, BATCH), tb32x8>>>(xt, out);
}

// round 16
// speedup vs baseline: 1.0575x; 1.0575x over previous
#include <cuda_runtime.h>
#include <cuda_bf16.h>
#include <cuda_fp8.h>
#include <cstdint>
#include <math.h>

#define BATCH 32
#define CDIM  384
#define HDIM  56
#define HWSZ  3136
#define NTOK  100352
#define HID   1536
#define HEADS 8
#define HD    48
#define GSZ   7
#define SPR   8

typedef __nv_bfloat16 bf16;
typedef __nv_fp8_e4m3 fp8;

#define WSCALE     64.0f
#define INV_WSCALE 0.015625f

// ---------------- scratch ----------------
__device__ float g_xt  [(size_t)NTOK * CDIM];
__device__ fp8   g_h8  [(size_t)NTOK * CDIM];
__device__ bf16  g_qkvb[(size_t)NTOK * 3 * CDIM];
__device__ bf16  g_mb  [(size_t)NTOK * HID];
__device__ fp8   g_mg8 [(size_t)NTOK * HID];
__device__ fp8   g_wqkv8 [3 * CDIM * CDIM];
__device__ fp8   g_wproj8[CDIM * CDIM];
__device__ fp8   g_wfc18 [HID * CDIM];
__device__ fp8   g_wfc28 [CDIM * HID];

__device__ __forceinline__ unsigned int saddr(const void* p) {
    return (unsigned int)__cvta_generic_to_shared(p);
}
__device__ __forceinline__ void cp16(unsigned int dst, const void* src) {
    asm volatile("cp.async.cg.shared.global [%0], [%1], 16;" :: "r"(dst), "l"(src));
}

// ================== FP8 e4m3 tensor-core GEMM ==================
// Block 128x128, 8 warps (warp tile 64x32), BK=128 bytes, 2-stage ring, 2 CTAs/SM.
// Pointer-increment loader + hoisted ldmatrix bases (validated R15); STG=2 (validated R14).
#define PADB 144
#define STG 2
#define TILEB (128 * PADB)

template<int EPI>
__global__ __launch_bounds__(256, 2) void gemm_fp8_kernel(
    const fp8* __restrict__ A, const fp8* __restrict__ Bw,
    const float* __restrict__ bias, const float* __restrict__ res,
    const float* __restrict__ gamma, void* __restrict__ Cout,
    int M, int N, int K)
{
    extern __shared__ char sm8[];
    char* As = sm8;
    char* Bs = sm8 + STG * TILEB;

    const int tid  = threadIdx.x;
    const int lane = tid & 31;
    const int warp = tid >> 5;
    const int wm   = (warp >> 2) * 64;
    const int wn   = (warp & 3) * 32;
    const int bm   = blockIdx.y * 128;
    const int bn   = blockIdx.x * 128;

    float acc[4][4][4];
#pragma unroll
    for (int i = 0; i < 4; i++)
#pragma unroll
        for (int j = 0; j < 4; j++)
#pragma unroll
            for (int r = 0; r < 4; r++) acc[i][j][r] = 0.f;

    // ---- precomputed loader state ----
    const char* aptr[4];
    const char* bptr[4];
    unsigned int dA0[4], dB0[4];
#pragma unroll
    for (int u = 0; u < 4; u++) {
        int id = u * 256 + tid;
        int row = id >> 3, c = id & 7;
        aptr[u] = (const char*)A + (size_t)(bm + row) * K + c * 16;
        bptr[u] = (const char*)Bw + (size_t)(bn + row) * K + c * 16;
        dA0[u] = saddr(As + row * PADB + c * 16);
        dB0[u] = saddr(Bs + row * PADB + c * 16);
    }

    // ---- hoisted ldmatrix bases (stage-0) ----
    const int a_row  = lane & 15;
    const int a_kb   = (lane >> 4) * 16;
    const int b_nrow = ((lane >> 4) * 8) + (lane & 7);
    const int b_kb   = ((lane >> 3) & 1) * 16;
    unsigned int sm_a[4], sm_b[2];
#pragma unroll
    for (int i = 0; i < 4; i++)
        sm_a[i] = saddr(As + (wm + i * 16 + a_row) * PADB + a_kb);
#pragma unroll
    for (int j2 = 0; j2 < 2; j2++)
        sm_b[j2] = saddr(Bs + (wn + j2 * 16 + b_nrow) * PADB + b_kb);

    const int iters = K / 128;

    auto load_stage = [&](int s) {
        const unsigned int so = (unsigned int)(s * TILEB);
#pragma unroll
        for (int u = 0; u < 4; u++) {
            cp16(dA0[u] + so, aptr[u]);
            aptr[u] += 128;
        }
#pragma unroll
        for (int u = 0; u < 4; u++) {
            cp16(dB0[u] + so, bptr[u]);
            bptr[u] += 128;
        }
        asm volatile("cp.async.commit_group;");
    };

    load_stage(0);
    if (iters > 1) load_stage(1);

    for (int it = 0; it < iters; it++) {
        if (it + 1 < iters)
            asm volatile("cp.async.wait_group 1;" ::: "memory");
        else
            asm volatile("cp.async.wait_group 0;" ::: "memory");
        __syncthreads();

        const unsigned int so = (unsigned int)((it & 1) * TILEB);

#pragma unroll
        for (int ks = 0; ks < 4; ks++) {
            unsigned int a[4][4];
#pragma unroll
            for (int i = 0; i < 4; i++) {
                unsigned int ad = sm_a[i] + so + ks * 32;
                asm volatile("ldmatrix.sync.aligned.m8n8.x4.shared.b16 {%0,%1,%2,%3}, [%4];"
                             : "=r"(a[i][0]), "=r"(a[i][1]), "=r"(a[i][2]), "=r"(a[i][3])
                             : "r"(ad));
            }
            unsigned int b[4][2];
#pragma unroll
            for (int j2 = 0; j2 < 2; j2++) {
                unsigned int bd = sm_b[j2] + so + ks * 32;
                unsigned int r0, r1, r2, r3;
                asm volatile("ldmatrix.sync.aligned.m8n8.x4.shared.b16 {%0,%1,%2,%3}, [%4];"
                             : "=r"(r0), "=r"(r1), "=r"(r2), "=r"(r3) : "r"(bd));
                b[j2 * 2 + 0][0] = r0; b[j2 * 2 + 0][1] = r1;
                b[j2 * 2 + 1][0] = r2; b[j2 * 2 + 1][1] = r3;
            }
#pragma unroll
            for (int i = 0; i < 4; i++)
#pragma unroll
                for (int j = 0; j < 4; j++)
                    asm volatile(
                        "mma.sync.aligned.m16n8k32.row.col.f32.e4m3.e4m3.f32 "
                        "{%0,%1,%2,%3}, {%4,%5,%6,%7}, {%8,%9}, {%0,%1,%2,%3};"
                        : "+f"(acc[i][j][0]), "+f"(acc[i][j][1]),
                          "+f"(acc[i][j][2]), "+f"(acc[i][j][3])
                        : "r"(a[i][0]), "r"(a[i][1]), "r"(a[i][2]), "r"(a[i][3]),
                          "r"(b[j][0]), "r"(b[j][1]));
        }
        __syncthreads();
        if (it + 2 < iters) load_stage(it & 1);
    }

    // -------- epilogue --------
    const int rbase = bm + wm + (lane >> 2);
    const int cbase = bn + wn + (lane & 3) * 2;
#pragma unroll
    for (int j = 0; j < 4; j++) {
        const int c = cbase + j * 8;
        const float b0 = bias ? bias[c] : 0.f;
        const float b1 = bias ? bias[c + 1] : 0.f;
        float g0 = 1.f, g1 = 1.f;
        if (EPI == 1) { g0 = gamma[c]; g1 = gamma[c + 1]; }
#pragma unroll
        for (int i = 0; i < 4; i++) {
#pragma unroll
            for (int h = 0; h < 2; h++) {
                const int r = rbase + i * 16 + h * 8;
                const float v0 = acc[i][j][h * 2 + 0] * INV_WSCALE + b0;
                const float v1 = acc[i][j][h * 2 + 1] * INV_WSCALE + b1;
                if (EPI == 0) {
                    bf16* C = (bf16*)Cout;
                    __nv_bfloat162 pv;
                    pv.x = __float2bfloat16(v0);
                    pv.y = __float2bfloat16(v1);
                    *(__nv_bfloat162*)&C[(size_t)r * N + c] = pv;
                } else {
                    float* C = (float*)Cout;
                    float2 rr = *(const float2*)&res[(size_t)r * N + c];
                    float2 o;
                    o.x = rr.x + g0 * v0;
                    o.y = rr.y + g1 * v1;
                    *(float2*)&C[(size_t)r * N + c] = o;
                }
            }
        }
    }
}
#define GEMM_SMEM (STG * 2 * TILEB)

// ---------------- merged weight transpose+convert ----------------
__global__ void wconv_all_kernel(const float* __restrict__ qkv_w, const float* __restrict__ proj_w,
                                 const float* __restrict__ fc1_w, const float* __restrict__ fc2_w,
                                 fp8* __restrict__ wq, fp8* __restrict__ wp,
                                 fp8* __restrict__ w1, fp8* __restrict__ w2) {
    const float* w; fp8* o; int K, N;
    switch (blockIdx.z) {
        case 0: w = qkv_w;  o = wq; K = CDIM; N = 3 * CDIM; break;
        case 1: w = proj_w; o = wp; K = CDIM; N = CDIM;     break;
        case 2: w = fc1_w;  o = w1; K = CDIM; N = HID;      break;
        default:w = fc2_w;  o = w2; K = HID;  N = CDIM;     break;
    }
    const int n0 = blockIdx.x * 32, k0 = blockIdx.y * 32;
    if (n0 >= N || k0 >= K) return;
    __shared__ float tile[32][33];
#pragma unroll
    for (int i = 0; i < 4; i++)
        tile[threadIdx.y + i * 8][threadIdx.x] =
            w[(size_t)(k0 + threadIdx.y + i * 8) * N + n0 + threadIdx.x];
    __syncthreads();
#pragma unroll
    for (int i = 0; i < 4; i++)
        o[(size_t)(n0 + threadIdx.y + i * 8) * K + k0 + threadIdx.x] =
            fp8(tile[threadIdx.x][threadIdx.y + i * 8] * WSCALE);
}

// ---------------- transposes ----------------
__global__ void transpose_in_kernel(const float* __restrict__ x, float* __restrict__ xt) {
    __shared__ float tile[32][33];
    const int b = blockIdx.z, p0 = blockIdx.x * 32, c0 = blockIdx.y * 32;
    const float* xb = x + (size_t)b * CDIM * HWSZ;
#pragma unroll
    for (int i = 0; i < 4; i++)
        tile[threadIdx.y + i * 8][threadIdx.x] =
            xb[(size_t)(c0 + threadIdx.y + i * 8) * HWSZ + p0 + threadIdx.x];
    __syncthreads();
#pragma unroll
    for (int i = 0; i < 4; i++)
        xt[((size_t)b * HWSZ + p0 + threadIdx.y + i * 8) * CDIM + c0 + threadIdx.x] =
            tile[threadIdx.x][threadIdx.y + i * 8];
}
__global__ void transpose_out_kernel(const float* __restrict__ xt, float* __restrict__ out) {
    __shared__ float tile[32][33];
    const int b = blockIdx.z, p0 = blockIdx.x * 32, c0 = blockIdx.y * 32;
#pragma unroll
    for (int i = 0; i < 4; i++)
        tile[threadIdx.y + i * 8][threadIdx.x] =
            xt[((size_t)b * HWSZ + p0 + threadIdx.y + i * 8) * CDIM + c0 + threadIdx.x];
    __syncthreads();
    float* ob = out + (size_t)b * CDIM * HWSZ;
#pragma unroll
    for (int i = 0; i < 4; i++)
        ob[(size_t)(c0 + threadIdx.y + i * 8) * HWSZ + p0 + threadIdx.x] =
            tile[threadIdx.x][threadIdx.y + i * 8];
}

// ---------------- LayerNorm (fp32 in, fp8 out) ----------------
__global__ void ln_kernel(const float* __restrict__ in, fp8* __restrict__ out,
                          const float* __restrict__ g, const float* __restrict__ b) {
    const int row = blockIdx.x * 8 + threadIdx.y;
    const int lane = threadIdx.x;
    const float* xr = in + (size_t)row * CDIM;
    float v[12];
    float s = 0.f;
#pragma unroll
    for (int i = 0; i < 12; i++) { v[i] = xr[lane + i * 32]; s += v[i]; }
#pragma unroll
    for (int o = 16; o > 0; o >>= 1) s += __shfl_xor_sync(0xffffffffu, s, o);
    const float mean = s * (1.f / CDIM);
    float q = 0.f;
#pragma unroll
    for (int i = 0; i < 12; i++) { float d = v[i] - mean; q += d * d; }
#pragma unroll
    for (int o = 16; o > 0; o >>= 1) q += __shfl_xor_sync(0xffffffffu, q, o);
    const float r = rsqrtf(q * (1.f / CDIM) + 1e-5f);
    fp8* orow = out + (size_t)row * CDIM;
#pragma unroll
    for (int i = 0; i < 12; i++) {
        int c = lane + i * 32;
        orow[c] = fp8((v[i] - mean) * r * g[c] + b[c]);
    }
}

// ---------------- attention: 4 heads/block, reg scores, uint4 KV ----------------
__global__ __launch_bounds__(256) void attn_kernel(const bf16* __restrict__ qkv,
                                                   fp8* __restrict__ o) {
    __shared__ uint4 sk[4][64][6];
    __shared__ uint4 sv[4][64][6];
    __shared__ int   srow[64];

    const int tid = threadIdx.x;
    const int wnd = blockIdx.x;
    const int hg  = blockIdx.y * 4;
    const int b   = wnd / (GSZ * GSZ);
    const int gy  = (wnd / GSZ) % GSZ;
    const int gx  = wnd % GSZ;

    if (tid < 64) {
        int sy = tid / SPR, sx = tid % SPR;
        srow[tid] = b * HWSZ + (sy * GSZ + gy) * HDIM + (sx * GSZ + gx);
    }
    __syncthreads();

    for (int id = tid; id < 1536; id += 256) {
        int h = id / 384, rem = id % 384;
        int t = rem / 6, q = rem % 6;
        size_t base = (size_t)srow[t] * (3 * CDIM) + (hg + h) * HD + q * 8;
        sk[h][t][q] = *(const uint4*)&qkv[base + CDIM];
        sv[h][t][q] = *(const uint4*)&qkv[base + 2 * CDIM];
    }
    __syncthreads();

    const int h = tid >> 6;
    const int t = tid & 63;
    const float scale = 0.14433756729740643f;

    const uint4* qp = (const uint4*)(qkv + (size_t)srow[t] * (3 * CDIM) + (hg + h) * HD);
    uint4 qv[6];
#pragma unroll
    for (int u = 0; u < 6; u++) qv[u] = qp[u];
    const __nv_bfloat162* q2 = (const __nv_bfloat162*)qv;

    float sc[64];
#pragma unroll 4
    for (int j = 0; j < 64; j++) {
        const __nv_bfloat162* kr = (const __nv_bfloat162*)sk[h][j];
        __nv_bfloat162 a2 = __floats2bfloat162_rn(0.f, 0.f);
#pragma unroll
        for (int u = 0; u < 24; u++) a2 = __hfma2(q2[u], kr[u], a2);
        sc[j] = (__low2float(a2) + __high2float(a2)) * scale;
    }

    float mx = -1e30f;
#pragma unroll
    for (int j = 0; j < 64; j++) mx = fmaxf(mx, sc[j]);
    float sum = 0.f;
#pragma unroll
    for (int j = 0; j < 64; j++) {
        float p = __expf(sc[j] - mx);
        sc[j] = p; sum += p;
    }
    const float inv = 1.f / sum;

    __nv_bfloat162 oacc[24];
#pragma unroll
    for (int u = 0; u < 24; u++) oacc[u] = __floats2bfloat162_rn(0.f, 0.f);
#pragma unroll 4
    for (int j = 0; j < 64; j++) {
        const __nv_bfloat162* vr = (const __nv_bfloat162*)sv[h][j];
        __nv_bfloat162 p2 = __float2bfloat162_rn(sc[j]);
#pragma unroll
        for (int u = 0; u < 24; u++) oacc[u] = __hfma2(p2, vr[u], oacc[u]);
    }

    unsigned int packed[12];
#pragma unroll
    for (int u = 0; u < 12; u++) {
        float4 f4 = make_float4(__low2float(oacc[2 * u]) * inv,
                                __high2float(oacc[2 * u]) * inv,
                                __low2float(oacc[2 * u + 1]) * inv,
                                __high2float(oacc[2 * u + 1]) * inv);
        __nv_fp8x4_e4m3 p4(f4);
        packed[u] = *(unsigned int*)&p4;
    }
    uint4* op = (uint4*)(o + (size_t)srow[t] * CDIM + (hg + h) * HD);
#pragma unroll
    for (int u = 0; u < 3; u++)
        op[u] = make_uint4(packed[4 * u], packed[4 * u + 1], packed[4 * u + 2], packed[4 * u + 3]);
}

// ---------------- depthwise 3x3 + GELU, smem row-tiled ----------------
__global__ __launch_bounds__(256) void dwconv_gelu_kernel(
    const bf16* __restrict__ m, const float* __restrict__ w,
    const float* __restrict__ bias, fp8* __restrict__ out)
{
    __shared__ __nv_bfloat162 srow[3][56][64];
    __shared__ __nv_bfloat162 sw[9][64];
    __shared__ float2 sb[64];

    const int tid = threadIdx.x;
    const int y   = blockIdx.x;
    const int cc  = blockIdx.y * 128;
    const int b   = blockIdx.z;

    for (int i = tid; i < 576; i += 256) {
        int t = i / 64, cp = i % 64;
        sw[t][cp] = __floats2bfloat162_rn(w[(cc + 2 * cp) * 9 + t],
                                          w[(cc + 2 * cp + 1) * 9 + t]);
    }
    if (tid < 64) sb[tid] = make_float2(bias[cc + 2 * tid], bias[cc + 2 * tid + 1]);

    const uint4 zero4 = make_uint4(0, 0, 0, 0);
#pragma unroll
    for (int r = 0; r < 3; r++) {
        int yy = y + r - 1;
        const bool ok = (yy >= 0) && (yy < HDIM);
        const bf16* src = m + ((size_t)b * HWSZ + yy * HDIM) * HID + cc;
        for (int id = tid; id < 896; id += 256) {
            int x = id >> 4, c8 = id & 15;
            uint4 v = ok ? *(const uint4*)(src + (size_t)x * HID + c8 * 8) : zero4;
            *(uint4*)&srow[r][x][c8 * 4] = v;
        }
    }
    __syncthreads();

    const float kk = 0.70710678118654752f;
    fp8* orow = out + ((size_t)b * HWSZ + y * HDIM) * HID + cc;

    for (int it = tid; it < 56 * 64; it += 256) {
        int cp = it & 63, x = it >> 6;
        __nv_bfloat162 acc = __floats2bfloat162_rn(0.f, 0.f);
#pragma unroll
        for (int r = 0; r < 3; r++) {
#pragma unroll
            for (int kx = -1; kx <= 1; kx++) {
                int xx = x + kx;
                if (xx >= 0 && xx < HDIM)
                    acc = __hfma2(srow[r][xx][cp], sw[r * 3 + kx + 1][cp], acc);
            }
        }
        float2 bb = sb[cp];
        float a0 = __low2float(acc) + bb.x;
        float a1 = __high2float(acc) + bb.y;
        __nv_fp8x2_e4m3 pv(make_float2(0.5f * a0 * (1.f + erff(a0 * kk)),
                                       0.5f * a1 * (1.f + erff(a1 * kk))));
        *(__nv_fp8x2_e4m3*)&orow[(size_t)x * HID + 2 * cp] = pv;
    }
}

// ---------------- launch ----------------
extern "C" void kernel_launch(void* const* d_in, const int* in_sizes, int n_in,
                              void* d_out, int out_size) {
    const float* x      = (const float*)d_in[0];
    const float* ln1_g  = (const float*)d_in[1];
    const float* ln1_b  = (const float*)d_in[2];
    const float* qkv_w  = (const float*)d_in[3];
    const float* proj_w = (const float*)d_in[4];
    const float* proj_b = (const float*)d_in[5];
    const float* ln2_g  = (const float*)d_in[6];
    const float* ln2_b  = (const float*)d_in[7];
    const float* fc1_w  = (const float*)d_in[8];
    const float* fc1_b  = (const float*)d_in[9];
    const float* dw_w   = (const float*)d_in[10];
    const float* dw_b   = (const float*)d_in[11];
    const float* fc2_w  = (const float*)d_in[12];
    const float* fc2_b  = (const float*)d_in[13];
    const float* gamma1 = (const float*)d_in[14];
    const float* gamma2 = (const float*)d_in[15];
    float* out = (float*)d_out;

    float *xt; bf16 *qkvb, *mb; fp8 *h8, *mg8, *wq, *wp, *w1, *w2;
    cudaGetSymbolAddress((void**)&xt,   g_xt);
    cudaGetSymbolAddress((void**)&h8,   g_h8);
    cudaGetSymbolAddress((void**)&qkvb, g_qkvb);
    cudaGetSymbolAddress((void**)&mb,   g_mb);
    cudaGetSymbolAddress((void**)&mg8,  g_mg8);
    cudaGetSymbolAddress((void**)&wq,   g_wqkv8);
    cudaGetSymbolAddress((void**)&wp,   g_wproj8);
    cudaGetSymbolAddress((void**)&w1,   g_wfc18);
    cudaGetSymbolAddress((void**)&w2,   g_wfc28);

    static bool attr_done = false;
    if (!attr_done) {
        cudaFuncSetAttribute(gemm_fp8_kernel<0>,
                             cudaFuncAttributeMaxDynamicSharedMemorySize, GEMM_SMEM);
        cudaFuncSetAttribute(gemm_fp8_kernel<1>,
                             cudaFuncAttributeMaxDynamicSharedMemorySize, GEMM_SMEM);
        attr_done = true;
    }

    dim3 tb32x8(32, 8);

    wconv_all_kernel<<<dim3(48, 48, 4), tb32x8>>>(qkv_w, proj_w, fc1_w, fc2_w,
                                                  wq, wp, w1, w2);
    transpose_in_kernel<<<dim3(HWSZ / 32, CDIM / 32, BATCH), tb32x8>>>(x, xt);
    ln_kernel<<<NTOK / 8, tb32x8>>>(xt, h8, ln1_g, ln1_b);

    gemm_fp8_kernel<0><<<dim3(1152 / 128, NTOK / 128), 256, GEMM_SMEM>>>(
        h8, wq, nullptr, nullptr, nullptr, qkvb, NTOK, 1152, CDIM);
    attn_kernel<<<dim3(BATCH * GSZ * GSZ, HEADS / 4), 256>>>(qkvb, h8);
    gemm_fp8_kernel<1><<<dim3(CDIM / 128, NTOK / 128), 256, GEMM_SMEM>>>(
        h8, wp, proj_b, xt, gamma1, xt, NTOK, CDIM, CDIM);
    ln_kernel<<<NTOK / 8, tb32x8>>>(xt, h8, ln2_g, ln2_b);
    gemm_fp8_kernel<0><<<dim3(HID / 128, NTOK / 128), 256, GEMM_SMEM>>>(
        h8, w1, fc1_b, nullptr, nullptr, mb, NTOK, HID, CDIM);
    dwconv_gelu_kernel<<<dim3(HDIM, HID / 128, BATCH), 256>>>(mb, dw_w, dw_b, mg8);
    gemm_fp8_kernel<1><<<dim3(CDIM / 128, NTOK / 128), 256, GEMM_SMEM>>>(
        mg8, w2, fc2_b, xt, gamma2, xt, NTOK, CDIM, HID);

    transpose_out_kernel<<<dim3(HWSZ / 32, CDIM / 32, BATCH), tb32x8>>>(xt, out);
}